// round 6
// baseline (speedup 1.0000x reference)
#include <cuda_runtime.h>

// GlobalFilter: y = irfft2(rfft2(x, ortho) * W, ortho)
// x: [128,14,14,768] f32, W: [14,8,768,2] f32.
// R6: register-diet for 5 CTAs/SM. Pass B stages weighted X through its
//     private smem column slots (fwd/inv reg sets no longer co-live);
//     fold-on-load in passes A/B. Packed f32x2 (FFMA2) throughout.

#define CC  768
#define CB  32
#define NTH 256

typedef unsigned long long ull;

__device__ __forceinline__ ull pk(float lo, float hi) {
    ull r; asm("mov.b64 %0, {%1,%2};" : "=l"(r) : "f"(lo), "f"(hi)); return r;
}
__device__ __forceinline__ void upk(ull v, float& lo, float& hi) {
    asm("mov.b64 {%0,%1}, %2;" : "=f"(lo), "=f"(hi) : "l"(v));
}
__device__ __forceinline__ ull f2fma(ull a, ull b, ull c) {
    ull d; asm("fma.rn.f32x2 %0, %1, %2, %3;" : "=l"(d) : "l"(a), "l"(b), "l"(c)); return d;
}
__device__ __forceinline__ ull f2add(ull a, ull b) {
    ull d; asm("add.rn.f32x2 %0, %1, %2;" : "=l"(d) : "l"(a), "l"(b)); return d;
}
__device__ __forceinline__ ull f2sub(ull a, ull b) {
    ull d; asm("sub.rn.f32x2 %0, %1, %2;" : "=l"(d) : "l"(a), "l"(b)); return d;
}
__host__ __device__ constexpr ull pkc(float lo, float hi) {
    return (ull)__builtin_bit_cast(unsigned int, lo)
         | ((ull)__builtin_bit_cast(unsigned int, hi) << 32);
}
// complex multiply (packed X) by float2 weight
__device__ __forceinline__ ull cmulw(ull X, float2 w) {
    float xr, xi; upk(X, xr, xi);
    return pk(fmaf(-xi, w.y, xr * w.x), fmaf(xi, w.x, xr * w.y));
}

#define DEF_TWIDDLES \
    constexpr float COS14[14] = { \
         1.0f,                 0.9009688679024191f,  0.6234898018587336f, \
         0.22252093395631445f,-0.22252093395631445f,-0.6234898018587336f, \
        -0.9009688679024191f, -1.0f,                -0.9009688679024191f, \
        -0.6234898018587336f, -0.22252093395631445f, 0.22252093395631445f, \
         0.6234898018587336f,  0.9009688679024191f }; \
    constexpr float SIN14[14] = { \
         0.0f,                 0.43388373911755823f, 0.7818314824680298f, \
         0.9749279121818236f,  0.9749279121818236f,  0.7818314824680298f, \
         0.43388373911755823f, 0.0f,                -0.43388373911755823f, \
        -0.7818314824680298f, -0.9749279121818236f, -0.9749279121818236f, \
        -0.7818314824680298f, -0.43388373911755823f }

__global__ __launch_bounds__(NTH, 5)
void gfilter_kernel(const float* __restrict__ x,
                    const float* __restrict__ wt,
                    float* __restrict__ y)
{
    DEF_TWIDDLES;
    extern __shared__ ull sbuf[];   // 112 slots x 32 channels, 8B each

    const int tid  = threadIdx.x;
    const int cl   = tid & 31;
    const int role = tid >> 5;      // 0..7, one warp per role
    const int b    = blockIdx.y;
    const int c    = blockIdx.x * CB + cl;

    ull* bufc = sbuf + cl;          // index: slot*32; slot = h*8 + kw
    const int base = (b * 196) * CC + c;
    const float* xb = x + base;

    // ---- Pass A: rfft over W on rows read straight from global -------------
    #pragma unroll
    for (int i = 0; i < 2; ++i) {
        const int h = role + 8 * i;
        if (i == 0 || role < 6) {
            const float x0 = xb[(h * 14 + 0) * CC];
            const float x7 = xb[(h * 14 + 7) * CC];
            ull eo[7];
            #pragma unroll
            for (int j = 1; j <= 6; ++j) {
                const float a  = xb[(h * 14 + j) * CC];
                const float bq = xb[(h * 14 + 14 - j) * CC];
                eo[j] = pk(a + bq, a - bq);
            }
            const float be = x0 + x7, bo = x0 - x7;
            #pragma unroll
            for (int kw = 0; kw < 8; ++kw) {
                ull acc = pk((kw & 1) ? bo : be, 0.f);   // (re, im)
                #pragma unroll
                for (int j = 1; j <= 6; ++j) {
                    const int m = (kw * j) % 14;
                    acc = f2fma(eo[j], pkc(COS14[m], -SIN14[m]), acc);
                }
                bufc[(h * 8 + kw) * 32] = acc;
            }
        }
    }
    __syncthreads();

    // ---- Pass B: fwd H-DFT + weight + inv H-DFT, one kw column per warp ----
    // All 14 column slots are private to this thread; weighted X is staged
    // through them between the forward and inverse halves (register diet).
    {
        const int kw = role;
        const float2* wt2c = reinterpret_cast<const float2*>(wt) + c;

        // forward folds over h (fold on load)
        ull E[7], O[7];
        const ull f0 = bufc[(0 * 8 + kw) * 32];
        const ull f7 = bufc[(7 * 8 + kw) * 32];
        #pragma unroll
        for (int j = 1; j <= 6; ++j) {
            const ull a  = bufc[(j * 8 + kw) * 32];
            const ull bq = bufc[((14 - j) * 8 + kw) * 32];
            E[j] = f2add(a, bq);
            O[j] = f2sub(a, bq);
        }
        const ull fbp = f2add(f0, f7);
        const ull fbm = f2sub(f0, f7);

        // forward per kh-pair, weight-multiply, stage X into own slots
        #pragma unroll
        for (int kh = 0; kh < 8; ++kh) {
            ull Cacc = (kh & 1) ? fbm : fbp;  // (Cr, Ci)
            ull Sacc = 0ull;                  // (Sr, Si)
            #pragma unroll
            for (int j = 1; j <= 6; ++j) {
                const int m = (kh * j) % 14;
                Cacc = f2fma(E[j], pkc(COS14[m], COS14[m]), Cacc);
                if ((m % 7) != 0)
                    Sacc = f2fma(O[j], pkc(SIN14[m], SIN14[m]), Sacc);
            }
            float sr, si; upk(Sacc, sr, si);
            // X[kh] = C - iS ; X[14-kh] = C + iS
            bufc[(kh * 8 + kw) * 32] =
                cmulw(f2add(Cacc, pk(si, -sr)), wt2c[(kh * 8 + kw) * CC]);
            if (kh >= 1 && kh <= 6)
                bufc[((14 - kh) * 8 + kw) * 32] =
                    cmulw(f2add(Cacc, pk(-si, sr)), wt2c[((14 - kh) * 8 + kw) * CC]);
        }

        // inverse H-DFT: reload X, fold, write Y1 back to same column
        ull EZ[7], OZ[7];
        const ull z0 = bufc[(0 * 8 + kw) * 32];
        const ull z7 = bufc[(7 * 8 + kw) * 32];
        #pragma unroll
        for (int j = 1; j <= 6; ++j) {
            const ull a  = bufc[(j * 8 + kw) * 32];
            const ull bq = bufc[((14 - j) * 8 + kw) * 32];
            EZ[j] = f2add(a, bq);
            OZ[j] = f2sub(a, bq);
        }
        const ull ibp = f2add(z0, z7);
        const ull ibm = f2sub(z0, z7);
        #pragma unroll
        for (int h = 0; h < 8; ++h) {
            ull Cacc = (h & 1) ? ibm : ibp;
            ull Sacc = 0ull;
            #pragma unroll
            for (int j = 1; j <= 6; ++j) {
                const int m = (j * h) % 14;
                Cacc = f2fma(EZ[j], pkc(COS14[m], COS14[m]), Cacc);
                if ((m % 7) != 0)
                    Sacc = f2fma(OZ[j], pkc(SIN14[m], SIN14[m]), Sacc);
            }
            float sr, si; upk(Sacc, sr, si);
            bufc[(h * 8 + kw) * 32] = f2add(Cacc, pk(-si, sr));
            if (h >= 1 && h <= 6)
                bufc[((14 - h) * 8 + kw) * 32] = f2add(Cacc, pk(si, -sr));
        }
    }
    __syncthreads();

    // ---- Pass C: c2r over W (w-paired) + ortho scale, write out ------------
    float* yb = y + base;
    #pragma unroll
    for (int i = 0; i < 2; ++i) {
        const int h = role + 8 * i;
        if (i == 0 || role < 6) {
            ull yv[8];
            #pragma unroll
            for (int kw = 0; kw < 8; ++kw)
                yv[kw] = bufc[(h * 8 + kw) * 32];
            float yr0, yi0, yr7, yi7;
            upk(yv[0], yr0, yi0); upk(yv[7], yr7, yi7);
            const float b0 = 0.5f * yr0, b7 = 0.5f * yr7;
            #pragma unroll
            for (int w = 0; w < 8; ++w) {
                ull acc = 0ull;                   // (Cv, Sv)
                #pragma unroll
                for (int kw = 1; kw <= 6; ++kw) {
                    const int m = (kw * w) % 14;
                    acc = f2fma(yv[kw], pkc(COS14[m], SIN14[m]), acc);
                }
                float Cv, Sv; upk(acc, Cv, Sv);
                const float bse = (w & 1) ? (b0 - b7) : (b0 + b7);
                yb[(h * 14 + w) * CC] = (bse + Cv - Sv) * (1.0f / 98.0f);
                if (w >= 1 && w <= 6)
                    yb[(h * 14 + 14 - w) * CC] = (bse + Cv + Sv) * (1.0f / 98.0f);
            }
        }
    }
}

extern "C" void kernel_launch(void* const* d_in, const int* in_sizes, int n_in,
                              void* d_out, int out_size)
{
    (void)in_sizes; (void)n_in; (void)out_size;
    const float* x  = (const float*)d_in[0];
    const float* wt = (const float*)d_in[1];
    float* y        = (float*)d_out;

    const int smem_bytes = 112 * CB * (int)sizeof(ull); // 28672
    dim3 grid(CC / CB, 128); // (24, 128)
    gfilter_kernel<<<grid, NTH, smem_bytes>>>(x, wt, y);
}